// round 2
// baseline (speedup 1.0000x reference)
#include <cuda_runtime.h>
#include <cuda_bf16.h>
#include <math.h>

// ---------------------------------------------------------------------------
// Problem constants
// ---------------------------------------------------------------------------
constexpr int CB     = 2;
constexpr int CN     = 2048;
constexpr int CD     = 768;
constexpr int CH     = 12;
constexpr int CDH    = 64;       // CD / CH
constexpr int CDEPTH = 4;
constexpr int CFF    = 3072;     // 4*CD
constexpr int CROWS  = CB * CN;  // 4096
constexpr float CSCALE = 0.125f; // CDH^-0.5
constexpr float CEPS   = 1e-5f;

// ---------------------------------------------------------------------------
// Scratch (static device globals -- no allocations allowed)
// ---------------------------------------------------------------------------
__device__ float g_x  [CROWS * CD];        // running residual stream   (12.6MB)
__device__ float g_xn [CROWS * CD];        // normalized x
__device__ float g_cn [CROWS * CD];        // normalized context
__device__ float g_qkv[CROWS * 3 * CD];    // packed q|k|v              (37.7MB)
__device__ float g_o  [CROWS * CD];        // merged attention output
__device__ float g_h  [CROWS * CFF];       // FFN hidden                (50.3MB)

// ---------------------------------------------------------------------------
// Reductions
// ---------------------------------------------------------------------------
__device__ __forceinline__ float warpSum(float v) {
#pragma unroll
    for (int o = 16; o; o >>= 1) v += __shfl_xor_sync(0xffffffffu, v, o);
    return v;
}
__device__ __forceinline__ float blockSum(float v) {
    __shared__ float sh[32];
    int lane = threadIdx.x & 31, w = threadIdx.x >> 5;
    v = warpSum(v);
    if (!lane) sh[w] = v;
    __syncthreads();
    if (w == 0) {
        v = (lane < (int)(blockDim.x >> 5)) ? sh[lane] : 0.f;
        v = warpSum(v);
        if (!lane) sh[0] = v;
    }
    __syncthreads();
    float r = sh[0];
    __syncthreads();
    return r;
}

// ---------------------------------------------------------------------------
// LayerNorm over D=768, one 256-thread block per row
// ---------------------------------------------------------------------------
__global__ void layernorm_k(const float* __restrict__ X, float* __restrict__ Y,
                            const float* __restrict__ w, const float* __restrict__ b) {
    long row = blockIdx.x;
    const float* x = X + row * CD;
    float* y = Y + row * CD;
    int t = threadIdx.x;
    float v0 = x[t], v1 = x[t + 256], v2 = x[t + 512];
    float m = blockSum(v0 + v1 + v2) * (1.0f / CD);
    float d0 = v0 - m, d1 = v1 - m, d2 = v2 - m;
    float var = blockSum(d0 * d0 + d1 * d1 + d2 * d2) * (1.0f / CD);
    float r = rsqrtf(var + CEPS);
    y[t]       = d0 * r * w[t]       + b[t];
    y[t + 256] = d1 * r * w[t + 256] + b[t + 256];
    y[t + 512] = d2 * r * w[t + 512] + b[t + 512];
}

// ---------------------------------------------------------------------------
// Fused flash attention.
//   One block = 64 query rows of one (b, h). 256 threads as 16x16, each
//   owning a 4x4 micro-tile. DH = 64 kept resident. Online softmax.
//   qkv layout: [b*N + n][3*D], q at col h*DH, k at D + h*DH, v at 2D + h*DH.
//   Output written merged: O[b*N + n][D] at col h*DH.
//   Shared (dynamic): Qs[64][68] (pre-scaled, [d][row]),
//                     KP[64][68] (K as [d][key], later reused as P [row][key]),
//                     Vs[64][68] ([key][d]).
// ---------------------------------------------------------------------------
constexpr int FPAD = 68;
constexpr int FSMEM = 3 * 64 * FPAD * (int)sizeof(float); // 52224 bytes

__global__ __launch_bounds__(256) void flash_k(const float* __restrict__ qkv,
                                               const float* __restrict__ rpb,
                                               float* __restrict__ O) {
    extern __shared__ float sm[];
    float* Qs = sm;                 // [64][FPAD]  (d-major)
    float* KP = sm + 64 * FPAD;     // [64][FPAD]  K (d-major) / P (row-major)
    float* Vs = sm + 2 * 64 * FPAD; // [64][FPAD]  (key-major)

    int z = blockIdx.y, b = z / CH, h = z % CH;
    const float* qb = qkv + (long)b * CN * 3 * CD + h * CDH;
    const float* kb = qb + CD;
    const float* vb = qb + 2 * CD;
    const float* bias = rpb + (long)h * CN * CN;
    float* ob = O + (long)b * CN * CD + h * CDH;

    int row0 = blockIdx.x * 64;
    int tid = threadIdx.x;
    int tx = tid & 15, ty = tid >> 4;

    // Load Q tile, transposed to [d][row], pre-scaled by 1/sqrt(DH)
    for (int e = tid; e < 64 * 16; e += 256) {
        int r = e >> 4, dv = (e & 15) << 2;
        float4 q4 = *(const float4*)(qb + (long)(row0 + r) * 3 * CD + dv);
        Qs[(dv + 0) * FPAD + r] = q4.x * CSCALE;
        Qs[(dv + 1) * FPAD + r] = q4.y * CSCALE;
        Qs[(dv + 2) * FPAD + r] = q4.z * CSCALE;
        Qs[(dv + 3) * FPAD + r] = q4.w * CSCALE;
    }

    float acc[4][4];
    float m[4], l[4];
#pragma unroll
    for (int i = 0; i < 4; i++) {
        m[i] = -1e30f; l[i] = 0.f;
#pragma unroll
        for (int j = 0; j < 4; j++) acc[i][j] = 0.f;
    }

    for (int j0 = 0; j0 < CN; j0 += 64) {
        __syncthreads();  // prev PV done (and Q visible on iter 0)
        // Load K (transposed to [d][key]) and V ([key][d])
        for (int e = tid; e < 64 * 16; e += 256) {
            int r = e >> 4, dv = (e & 15) << 2;
            float4 k4 = *(const float4*)(kb + (long)(j0 + r) * 3 * CD + dv);
            KP[(dv + 0) * FPAD + r] = k4.x;
            KP[(dv + 1) * FPAD + r] = k4.y;
            KP[(dv + 2) * FPAD + r] = k4.z;
            KP[(dv + 3) * FPAD + r] = k4.w;
            float4 v4 = *(const float4*)(vb + (long)(j0 + r) * 3 * CD + dv);
            *(float4*)(Vs + r * FPAD + dv) = v4;
        }
        __syncthreads();

        // S = Q @ K^T  (rows ty*4.., cols tx*4..)
        float s[4][4];
#pragma unroll
        for (int i = 0; i < 4; i++)
#pragma unroll
            for (int j = 0; j < 4; j++) s[i][j] = 0.f;
#pragma unroll 8
        for (int kk = 0; kk < 64; kk++) {
            float4 qa = *(const float4*)(Qs + kk * FPAD + ty * 4);
            float4 ka = *(const float4*)(KP + kk * FPAD + tx * 4);
            float qr[4] = {qa.x, qa.y, qa.z, qa.w};
            float kr[4] = {ka.x, ka.y, ka.z, ka.w};
#pragma unroll
            for (int i = 0; i < 4; i++)
#pragma unroll
                for (int j = 0; j < 4; j++) s[i][j] += qr[i] * kr[j];
        }
        // + relative position bias
#pragma unroll
        for (int i = 0; i < 4; i++) {
            float4 b4 = *(const float4*)(bias + (long)(row0 + ty * 4 + i) * CN + j0 + tx * 4);
            s[i][0] += b4.x; s[i][1] += b4.y; s[i][2] += b4.z; s[i][3] += b4.w;
        }

        // Online softmax update (row reductions across the 16 tx lanes)
#pragma unroll
        for (int i = 0; i < 4; i++) {
            float rm = fmaxf(fmaxf(s[i][0], s[i][1]), fmaxf(s[i][2], s[i][3]));
#pragma unroll
            for (int o = 8; o; o >>= 1) rm = fmaxf(rm, __shfl_xor_sync(0xffffffffu, rm, o));
            float nm = fmaxf(m[i], rm);
            float sc = __expf(m[i] - nm);
            float rs = 0.f;
#pragma unroll
            for (int j = 0; j < 4; j++) { s[i][j] = __expf(s[i][j] - nm); rs += s[i][j]; }
#pragma unroll
            for (int o = 8; o; o >>= 1) rs += __shfl_xor_sync(0xffffffffu, rs, o);
            m[i] = nm;
            l[i] = l[i] * sc + rs;
#pragma unroll
            for (int j = 0; j < 4; j++) acc[i][j] *= sc;
        }

        __syncthreads();  // all S reads of K done -> safe to overwrite as P
        // Store P as [row][key] (float4, conflict-free)
#pragma unroll
        for (int i = 0; i < 4; i++) {
            float4 p4 = make_float4(s[i][0], s[i][1], s[i][2], s[i][3]);
            *(float4*)(KP + (ty * 4 + i) * FPAD + tx * 4) = p4;
        }
        __syncthreads();

        // acc += P @ V
#pragma unroll 8
        for (int kk = 0; kk < 64; kk++) {
            float pr[4];
#pragma unroll
            for (int i = 0; i < 4; i++) pr[i] = KP[(ty * 4 + i) * FPAD + kk];
            float4 va = *(const float4*)(Vs + kk * FPAD + tx * 4);
            float vr[4] = {va.x, va.y, va.z, va.w};
#pragma unroll
            for (int i = 0; i < 4; i++)
#pragma unroll
                for (int j = 0; j < 4; j++) acc[i][j] += pr[i] * vr[j];
        }
    }

    // Normalize and write merged output
#pragma unroll
    for (int i = 0; i < 4; i++) {
        float inv = 1.0f / l[i];
        float4 o4 = make_float4(acc[i][0] * inv, acc[i][1] * inv,
                                acc[i][2] * inv, acc[i][3] * inv);
        *(float4*)(ob + (long)(row0 + ty * 4 + i) * CD + tx * 4) = o4;
    }
}

// ---------------------------------------------------------------------------
// Generic SGEMM (projections / FFN).  C = op(A @ B), row-major.
// Epilogues: 0: none   2: +bias[n] + residual[m,n]   3: gelu(acc + bias[n])
// ---------------------------------------------------------------------------
template <int BM, int BN, int BK, int TM, int TN, int EPI>
__global__ void gemm_k(const float* __restrict__ A, const float* __restrict__ B,
                       float* C,
                       int M, int N, int K, int lda, int ldb, int ldc,
                       const float* P, const float* R, int ldr) {
    constexpr int NT = (BM / TM) * (BN / TN);
    __shared__ float As[BK][BM];
    __shared__ float Bs[BK][BN];

    int tid = threadIdx.x;
    constexpr int TCOLS = BN / TN;
    int tx = tid % TCOLS, ty = tid / TCOLS;
    int row0 = blockIdx.y * BM;
    int col0 = blockIdx.x * BN;
    int trow = ty * TM, tcol = tx * TN;

    float acc[TM][TN];
#pragma unroll
    for (int i = 0; i < TM; i++)
#pragma unroll
        for (int j = 0; j < TN; j++) acc[i][j] = 0.f;

    for (int k0 = 0; k0 < K; k0 += BK) {
#pragma unroll
        for (int e = tid; e < BM * BK; e += NT) {
            int mm = e / BK, kk = e % BK;
            int gm = row0 + mm, gk = k0 + kk;
            As[kk][mm] = (gm < M && gk < K) ? A[(long)gm * lda + gk] : 0.f;
        }
#pragma unroll
        for (int e = tid; e < BN * BK; e += NT) {
            int kk = e / BN, nn = e % BN;
            int gn = col0 + nn, gk = k0 + kk;
            Bs[kk][nn] = (gn < N && gk < K) ? B[(long)gk * ldb + gn] : 0.f;
        }
        __syncthreads();
#pragma unroll
        for (int kk = 0; kk < BK; kk++) {
            float a[TM], bv[TN];
#pragma unroll
            for (int i = 0; i < TM; i += 4) {
                float4 t4 = *reinterpret_cast<const float4*>(&As[kk][trow + i]);
                a[i] = t4.x; a[i + 1] = t4.y; a[i + 2] = t4.z; a[i + 3] = t4.w;
            }
#pragma unroll
            for (int j = 0; j < TN; j += 4) {
                float4 t4 = *reinterpret_cast<const float4*>(&Bs[kk][tcol + j]);
                bv[j] = t4.x; bv[j + 1] = t4.y; bv[j + 2] = t4.z; bv[j + 3] = t4.w;
            }
#pragma unroll
            for (int i = 0; i < TM; i++)
#pragma unroll
                for (int j = 0; j < TN; j++) acc[i][j] += a[i] * bv[j];
        }
        __syncthreads();
    }

#pragma unroll
    for (int i = 0; i < TM; i++) {
        int gm = row0 + trow + i;
        if (gm >= M) continue;
#pragma unroll
        for (int j = 0; j < TN; j++) {
            int gn = col0 + tcol + j;
            if (gn >= N) continue;
            float v = acc[i][j];
            if (EPI == 2) {
                v = v + P[gn] + R[(long)gm * ldr + gn];
            } else if (EPI == 3) {
                v = v + P[gn];
                v = 0.5f * v * (1.0f + erff(v * 0.70710678118654752f));
            }
            C[(long)gm * ldc + gn] = v;
        }
    }
}

template <int EPI>
static void gemm(const float* A, const float* B, float* C,
                 int M, int N, int K, int lda, int ldb, int ldc,
                 const float* P = nullptr, const float* R = nullptr, int ldr = 0) {
    constexpr int BM = 128, BN = 128, BK = 8, TM = 8, TN = 8;
    dim3 grid((N + BN - 1) / BN, (M + BM - 1) / BM);
    dim3 blk((BM / TM) * (BN / TN));
    gemm_k<BM, BN, BK, TM, TN, EPI><<<grid, blk>>>(
        A, B, C, M, N, K, lda, ldb, ldc, P, R, ldr);
}

// ---------------------------------------------------------------------------
// kernel_launch
// ---------------------------------------------------------------------------
extern "C" void kernel_launch(void* const* d_in, const int* in_sizes, int n_in,
                              void* d_out, int out_size) {
    const float* in_x   = (const float*)d_in[0];
    const float* in_ctx = (const float*)d_in[1];
    const float* rpb    = (const float*)d_in[2];
    const float* ln1w   = (const float*)d_in[3];
    const float* ln1b   = (const float*)d_in[4];
    const float* w_qkv  = (const float*)d_in[5];
    const float* w_so   = (const float*)d_in[6];
    const float* b_so   = (const float*)d_in[7];
    const float* ln2w   = (const float*)d_in[8];
    const float* ln2b   = (const float*)d_in[9];
    const float* w_q    = (const float*)d_in[10];
    const float* w_k    = (const float*)d_in[11];
    const float* w_v    = (const float*)d_in[12];
    const float* w_co   = (const float*)d_in[13];
    const float* b_co   = (const float*)d_in[14];
    const float* ln3w   = (const float*)d_in[15];
    const float* ln3b   = (const float*)d_in[16];
    const float* w_f1   = (const float*)d_in[17];
    const float* b_f1   = (const float*)d_in[18];
    const float* w_f2   = (const float*)d_in[19];
    const float* b_f2   = (const float*)d_in[20];
    const float* lnow   = (const float*)d_in[21];
    const float* lnob   = (const float*)d_in[22];

    float *px, *pxn, *pcn, *pqkv, *po, *ph;
    cudaGetSymbolAddress((void**)&px,   g_x);
    cudaGetSymbolAddress((void**)&pxn,  g_xn);
    cudaGetSymbolAddress((void**)&pcn,  g_cn);
    cudaGetSymbolAddress((void**)&pqkv, g_qkv);
    cudaGetSymbolAddress((void**)&po,   g_o);
    cudaGetSymbolAddress((void**)&ph,   g_h);

    cudaFuncSetAttribute(flash_k, cudaFuncAttributeMaxDynamicSharedMemorySize, FSMEM);

    cudaMemcpyAsync(px, in_x, sizeof(float) * CROWS * CD, cudaMemcpyDeviceToDevice);

    dim3 fgrid(CN / 64, CB * CH);

    for (int i = 0; i < CDEPTH; i++) {
        // ---------------- self-attention ----------------
        layernorm_k<<<CROWS, 256>>>(px, pxn, ln1w + i * CD, ln1b + i * CD);
        gemm<0>(pxn, w_qkv + (long)i * CD * 3 * CD, pqkv,
                CROWS, 3 * CD, CD, CD, 3 * CD, 3 * CD);
        flash_k<<<fgrid, 256, FSMEM>>>(pqkv, rpb, po);
        gemm<2>(po, w_so + (long)i * CD * CD, px,
                CROWS, CD, CD, CD, CD, CD,
                b_so + i * CD, px, CD);

        // ---------------- cross-attention ----------------
        layernorm_k<<<CROWS, 256>>>(px,     pxn, ln2w + i * CD, ln2b + i * CD);
        layernorm_k<<<CROWS, 256>>>(in_ctx, pcn, ln2w + i * CD, ln2b + i * CD);
        gemm<0>(pxn, w_q + (long)i * CD * CD, pqkv,
                CROWS, CD, CD, CD, CD, 3 * CD);
        gemm<0>(pcn, w_k + (long)i * CD * CD, pqkv + CD,
                CROWS, CD, CD, CD, CD, 3 * CD);
        gemm<0>(pcn, w_v + (long)i * CD * CD, pqkv + 2 * CD,
                CROWS, CD, CD, CD, CD, 3 * CD);
        flash_k<<<fgrid, 256, FSMEM>>>(pqkv, rpb, po);
        gemm<2>(po, w_co + (long)i * CD * CD, px,
                CROWS, CD, CD, CD, CD, CD,
                b_co + i * CD, px, CD);

        // ---------------- FFN ----------------
        layernorm_k<<<CROWS, 256>>>(px, pxn, ln3w + i * CD, ln3b + i * CD);
        gemm<3>(pxn, w_f1 + (long)i * CD * CFF, ph,
                CROWS, CFF, CD, CD, CFF, CFF,
                b_f1 + i * CFF);
        gemm<2>(ph, w_f2 + (long)i * CFF * CD, px,
                CROWS, CD, CFF, CFF, CD, CD,
                b_f2 + i * CD, px, CD);
    }

    layernorm_k<<<CROWS, 256>>>(px, (float*)d_out, lnow, lnob);
}

// round 3
// speedup vs baseline: 2.3929x; 2.3929x over previous
#include <cuda_runtime.h>
#include <cuda_bf16.h>
#include <math.h>

// ---------------------------------------------------------------------------
// Problem constants
// ---------------------------------------------------------------------------
constexpr int CB     = 2;
constexpr int CN     = 2048;
constexpr int CD     = 768;
constexpr int CH     = 12;
constexpr int CDH    = 64;       // CD / CH
constexpr int CDEPTH = 4;
constexpr int CFF    = 3072;     // 4*CD
constexpr int CROWS  = CB * CN;  // 4096
constexpr float CSCALE = 0.125f; // CDH^-0.5
constexpr float CEPS   = 1e-5f;

// ---------------------------------------------------------------------------
// Scratch (static device globals -- no allocations allowed)
// ---------------------------------------------------------------------------
__device__ float g_x  [CROWS * CD];        // running residual stream
__device__ float g_xn [CROWS * CD];        // normalized x
__device__ float g_cn [CROWS * CD];        // normalized context
__device__ float g_qkv[CROWS * 3 * CD];    // packed q|k|v
__device__ float g_o  [CROWS * CD];        // merged attention output
__device__ float g_h  [CROWS * CFF];       // FFN hidden

// ---------------------------------------------------------------------------
// Reductions
// ---------------------------------------------------------------------------
__device__ __forceinline__ float warpSum(float v) {
#pragma unroll
    for (int o = 16; o; o >>= 1) v += __shfl_xor_sync(0xffffffffu, v, o);
    return v;
}
__device__ __forceinline__ float blockSum(float v) {
    __shared__ float sh[32];
    int lane = threadIdx.x & 31, w = threadIdx.x >> 5;
    v = warpSum(v);
    if (!lane) sh[w] = v;
    __syncthreads();
    if (w == 0) {
        v = (lane < (int)(blockDim.x >> 5)) ? sh[lane] : 0.f;
        v = warpSum(v);
        if (!lane) sh[0] = v;
    }
    __syncthreads();
    float r = sh[0];
    __syncthreads();
    return r;
}

// ---------------------------------------------------------------------------
// LayerNorm over D=768, one 256-thread block per row
// ---------------------------------------------------------------------------
__global__ void layernorm_k(const float* __restrict__ X, float* __restrict__ Y,
                            const float* __restrict__ w, const float* __restrict__ b) {
    long row = blockIdx.x;
    const float* x = X + row * CD;
    float* y = Y + row * CD;
    int t = threadIdx.x;
    float v0 = x[t], v1 = x[t + 256], v2 = x[t + 512];
    float m = blockSum(v0 + v1 + v2) * (1.0f / CD);
    float d0 = v0 - m, d1 = v1 - m, d2 = v2 - m;
    float var = blockSum(d0 * d0 + d1 * d1 + d2 * d2) * (1.0f / CD);
    float r = rsqrtf(var + CEPS);
    y[t]       = d0 * r * w[t]       + b[t];
    y[t + 256] = d1 * r * w[t + 256] + b[t + 256];
    y[t + 512] = d2 * r * w[t + 512] + b[t + 512];
}

// ---------------------------------------------------------------------------
// Fused flash attention (unchanged from passing R2 version).
// ---------------------------------------------------------------------------
constexpr int FPAD = 68;
constexpr int FSMEM = 3 * 64 * FPAD * (int)sizeof(float); // 52224 bytes

__global__ __launch_bounds__(256) void flash_k(const float* __restrict__ qkv,
                                               const float* __restrict__ rpb,
                                               float* __restrict__ O) {
    extern __shared__ float sm[];
    float* Qs = sm;
    float* KP = sm + 64 * FPAD;
    float* Vs = sm + 2 * 64 * FPAD;

    int z = blockIdx.y, b = z / CH, h = z % CH;
    const float* qb = qkv + (long)b * CN * 3 * CD + h * CDH;
    const float* kb = qb + CD;
    const float* vb = qb + 2 * CD;
    const float* bias = rpb + (long)h * CN * CN;
    float* ob = O + (long)b * CN * CD + h * CDH;

    int row0 = blockIdx.x * 64;
    int tid = threadIdx.x;
    int tx = tid & 15, ty = tid >> 4;

    for (int e = tid; e < 64 * 16; e += 256) {
        int r = e >> 4, dv = (e & 15) << 2;
        float4 q4 = *(const float4*)(qb + (long)(row0 + r) * 3 * CD + dv);
        Qs[(dv + 0) * FPAD + r] = q4.x * CSCALE;
        Qs[(dv + 1) * FPAD + r] = q4.y * CSCALE;
        Qs[(dv + 2) * FPAD + r] = q4.z * CSCALE;
        Qs[(dv + 3) * FPAD + r] = q4.w * CSCALE;
    }

    float acc[4][4];
    float m[4], l[4];
#pragma unroll
    for (int i = 0; i < 4; i++) {
        m[i] = -1e30f; l[i] = 0.f;
#pragma unroll
        for (int j = 0; j < 4; j++) acc[i][j] = 0.f;
    }

    for (int j0 = 0; j0 < CN; j0 += 64) {
        __syncthreads();
        for (int e = tid; e < 64 * 16; e += 256) {
            int r = e >> 4, dv = (e & 15) << 2;
            float4 k4 = *(const float4*)(kb + (long)(j0 + r) * 3 * CD + dv);
            KP[(dv + 0) * FPAD + r] = k4.x;
            KP[(dv + 1) * FPAD + r] = k4.y;
            KP[(dv + 2) * FPAD + r] = k4.z;
            KP[(dv + 3) * FPAD + r] = k4.w;
            float4 v4 = *(const float4*)(vb + (long)(j0 + r) * 3 * CD + dv);
            *(float4*)(Vs + r * FPAD + dv) = v4;
        }
        __syncthreads();

        float s[4][4];
#pragma unroll
        for (int i = 0; i < 4; i++)
#pragma unroll
            for (int j = 0; j < 4; j++) s[i][j] = 0.f;
#pragma unroll 8
        for (int kk = 0; kk < 64; kk++) {
            float4 qa = *(const float4*)(Qs + kk * FPAD + ty * 4);
            float4 ka = *(const float4*)(KP + kk * FPAD + tx * 4);
            float qr[4] = {qa.x, qa.y, qa.z, qa.w};
            float kr[4] = {ka.x, ka.y, ka.z, ka.w};
#pragma unroll
            for (int i = 0; i < 4; i++)
#pragma unroll
                for (int j = 0; j < 4; j++) s[i][j] += qr[i] * kr[j];
        }
#pragma unroll
        for (int i = 0; i < 4; i++) {
            float4 b4 = *(const float4*)(bias + (long)(row0 + ty * 4 + i) * CN + j0 + tx * 4);
            s[i][0] += b4.x; s[i][1] += b4.y; s[i][2] += b4.z; s[i][3] += b4.w;
        }

#pragma unroll
        for (int i = 0; i < 4; i++) {
            float rm = fmaxf(fmaxf(s[i][0], s[i][1]), fmaxf(s[i][2], s[i][3]));
#pragma unroll
            for (int o = 8; o; o >>= 1) rm = fmaxf(rm, __shfl_xor_sync(0xffffffffu, rm, o));
            float nm = fmaxf(m[i], rm);
            float sc = __expf(m[i] - nm);
            float rs = 0.f;
#pragma unroll
            for (int j = 0; j < 4; j++) { s[i][j] = __expf(s[i][j] - nm); rs += s[i][j]; }
#pragma unroll
            for (int o = 8; o; o >>= 1) rs += __shfl_xor_sync(0xffffffffu, rs, o);
            m[i] = nm;
            l[i] = l[i] * sc + rs;
#pragma unroll
            for (int j = 0; j < 4; j++) acc[i][j] *= sc;
        }

        __syncthreads();
#pragma unroll
        for (int i = 0; i < 4; i++) {
            float4 p4 = make_float4(s[i][0], s[i][1], s[i][2], s[i][3]);
            *(float4*)(KP + (ty * 4 + i) * FPAD + tx * 4) = p4;
        }
        __syncthreads();

#pragma unroll 8
        for (int kk = 0; kk < 64; kk++) {
            float pr[4];
#pragma unroll
            for (int i = 0; i < 4; i++) pr[i] = KP[(ty * 4 + i) * FPAD + kk];
            float4 va = *(const float4*)(Vs + kk * FPAD + tx * 4);
            float vr[4] = {va.x, va.y, va.z, va.w};
#pragma unroll
            for (int i = 0; i < 4; i++)
#pragma unroll
                for (int j = 0; j < 4; j++) acc[i][j] += pr[i] * vr[j];
        }
    }

#pragma unroll
    for (int i = 0; i < 4; i++) {
        float inv = 1.0f / l[i];
        float4 o4 = make_float4(acc[i][0] * inv, acc[i][1] * inv,
                                acc[i][2] * inv, acc[i][3] * inv);
        *(float4*)(ob + (long)(row0 + ty * 4 + i) * CD + tx * 4) = o4;
    }
}

// ---------------------------------------------------------------------------
// TF32 tensor-core GEMM.  C = op(A @ B), row-major, fp32 in/out.
//   BM=64, BN=128, BK=32. 8 warps as 2x4; warp tile 32x32 (2x4 m16n8k8 mmas).
//   Requires M%64==0, N%128==0, K%32==0 (true for all call sites).
// Epilogues: 0: none   2: +bias[n] + residual[m,n]   3: gelu(acc + bias[n])
// ---------------------------------------------------------------------------
constexpr int GBM = 64, GBN = 128, GBK = 32;
constexpr int ALD = GBK + 4;   // 36  (As row stride, conflict-free a-frags)
constexpr int BLD = GBN + 4;   // 132 (Bs row stride)

__device__ __forceinline__ unsigned f2tf32(float v) {
    unsigned r;
    asm("cvt.rna.tf32.f32 %0, %1;" : "=r"(r) : "f"(v));
    return r;
}

template <int EPI>
__global__ __launch_bounds__(256) void gemm_tf32_k(
        const float* __restrict__ A, const float* __restrict__ B, float* C,
        int M, int N, int K, int lda, int ldb, int ldc,
        const float* __restrict__ P, const float* __restrict__ R, int ldr) {
    __shared__ unsigned As[GBM * ALD];
    __shared__ unsigned Bs[GBK * BLD];

    int tid = threadIdx.x;
    int lane = tid & 31, wid = tid >> 5;
    int wm = wid >> 2, wn = wid & 3;            // 2 x 4 warp grid
    int row0 = blockIdx.y * GBM;
    int col0 = blockIdx.x * GBN;

    // global load coords
    int ar = tid >> 3, ac = (tid & 7) << 2;     // A: 2 rows (ar, ar+32) x 4 cols
    int br = tid >> 5, bc = (tid & 31) << 2;    // B: 4 rows (br+8i) x 4 cols

    const float* gA = A + (long)(row0 + ar) * lda + ac;
    const float* gB = B + (long)br * ldb + col0 + bc;

    float c[2][4][4];
#pragma unroll
    for (int mt = 0; mt < 2; mt++)
#pragma unroll
        for (int nt = 0; nt < 4; nt++)
#pragma unroll
            for (int e = 0; e < 4; e++) c[mt][nt][e] = 0.f;

    float4 aReg[2], bReg[4];
    // preload k0 = 0
    aReg[0] = *(const float4*)(gA);
    aReg[1] = *(const float4*)(gA + (long)32 * lda);
#pragma unroll
    for (int i = 0; i < 4; i++)
        bReg[i] = *(const float4*)(gB + (long)(8 * i) * ldb);

    for (int k0 = 0; k0 < K; k0 += GBK) {
        __syncthreads();
        // store converted tiles
#pragma unroll
        for (int h = 0; h < 2; h++) {
            unsigned* d = &As[(ar + 32 * h) * ALD + ac];
            d[0] = f2tf32(h ? aReg[1].x : aReg[0].x);
            d[1] = f2tf32(h ? aReg[1].y : aReg[0].y);
            d[2] = f2tf32(h ? aReg[1].z : aReg[0].z);
            d[3] = f2tf32(h ? aReg[1].w : aReg[0].w);
        }
#pragma unroll
        for (int i = 0; i < 4; i++) {
            unsigned* d = &Bs[(br + 8 * i) * BLD + bc];
            d[0] = f2tf32(bReg[i].x);
            d[1] = f2tf32(bReg[i].y);
            d[2] = f2tf32(bReg[i].z);
            d[3] = f2tf32(bReg[i].w);
        }
        __syncthreads();

        // prefetch next tile
        if (k0 + GBK < K) {
            const float* nA = gA + k0 + GBK;
            const float* nB = gB + (long)(k0 + GBK) * ldb;
            aReg[0] = *(const float4*)(nA);
            aReg[1] = *(const float4*)(nA + (long)32 * lda);
#pragma unroll
            for (int i = 0; i < 4; i++)
                bReg[i] = *(const float4*)(nB + (long)(8 * i) * ldb);
        }

        // compute 4 k8-steps
#pragma unroll
        for (int ks = 0; ks < 4; ks++) {
            int kb = ks * 8;
            unsigned af[2][4], bf[4][2];
#pragma unroll
            for (int mt = 0; mt < 2; mt++) {
                int r = wm * 32 + mt * 16 + (lane >> 2);
                int cx = kb + (lane & 3);
                af[mt][0] = As[r * ALD + cx];
                af[mt][1] = As[(r + 8) * ALD + cx];
                af[mt][2] = As[r * ALD + cx + 4];
                af[mt][3] = As[(r + 8) * ALD + cx + 4];
            }
#pragma unroll
            for (int nt = 0; nt < 4; nt++) {
                int cn = wn * 32 + nt * 8 + (lane >> 2);
                int rk = kb + (lane & 3);
                bf[nt][0] = Bs[rk * BLD + cn];
                bf[nt][1] = Bs[(rk + 4) * BLD + cn];
            }
#pragma unroll
            for (int mt = 0; mt < 2; mt++)
#pragma unroll
                for (int nt = 0; nt < 4; nt++) {
                    asm volatile(
                        "mma.sync.aligned.m16n8k8.row.col.f32.tf32.tf32.f32 "
                        "{%0,%1,%2,%3}, {%4,%5,%6,%7}, {%8,%9}, {%0,%1,%2,%3};"
                        : "+f"(c[mt][nt][0]), "+f"(c[mt][nt][1]),
                          "+f"(c[mt][nt][2]), "+f"(c[mt][nt][3])
                        : "r"(af[mt][0]), "r"(af[mt][1]), "r"(af[mt][2]), "r"(af[mt][3]),
                          "r"(bf[nt][0]), "r"(bf[nt][1]));
                }
        }
    }

    // epilogue: c0/c1 at (row, col), (row, col+1); c2/c3 at row+8
#pragma unroll
    for (int mt = 0; mt < 2; mt++) {
#pragma unroll
        for (int nt = 0; nt < 4; nt++) {
#pragma unroll
            for (int half = 0; half < 2; half++) {
                int gm = row0 + wm * 32 + mt * 16 + (lane >> 2) + 8 * half;
                int gn = col0 + wn * 32 + nt * 8 + (lane & 3) * 2;
                float v0 = c[mt][nt][half * 2 + 0];
                float v1 = c[mt][nt][half * 2 + 1];
                if (EPI == 2) {
                    v0 += P[gn]     + R[(long)gm * ldr + gn];
                    v1 += P[gn + 1] + R[(long)gm * ldr + gn + 1];
                } else if (EPI == 3) {
                    v0 += P[gn];
                    v1 += P[gn + 1];
                    v0 = 0.5f * v0 * (1.0f + erff(v0 * 0.70710678118654752f));
                    v1 = 0.5f * v1 * (1.0f + erff(v1 * 0.70710678118654752f));
                }
                C[(long)gm * ldc + gn]     = v0;
                C[(long)gm * ldc + gn + 1] = v1;
            }
        }
    }
}

template <int EPI>
static void gemm(const float* A, const float* B, float* C,
                 int M, int N, int K, int lda, int ldb, int ldc,
                 const float* P = nullptr, const float* R = nullptr, int ldr = 0) {
    dim3 grid(N / GBN, M / GBM);
    gemm_tf32_k<EPI><<<grid, 256>>>(A, B, C, M, N, K, lda, ldb, ldc, P, R, ldr);
}

// ---------------------------------------------------------------------------
// kernel_launch
// ---------------------------------------------------------------------------
extern "C" void kernel_launch(void* const* d_in, const int* in_sizes, int n_in,
                              void* d_out, int out_size) {
    const float* in_x   = (const float*)d_in[0];
    const float* in_ctx = (const float*)d_in[1];
    const float* rpb    = (const float*)d_in[2];
    const float* ln1w   = (const float*)d_in[3];
    const float* ln1b   = (const float*)d_in[4];
    const float* w_qkv  = (const float*)d_in[5];
    const float* w_so   = (const float*)d_in[6];
    const float* b_so   = (const float*)d_in[7];
    const float* ln2w   = (const float*)d_in[8];
    const float* ln2b   = (const float*)d_in[9];
    const float* w_q    = (const float*)d_in[10];
    const float* w_k    = (const float*)d_in[11];
    const float* w_v    = (const float*)d_in[12];
    const float* w_co   = (const float*)d_in[13];
    const float* b_co   = (const float*)d_in[14];
    const float* ln3w   = (const float*)d_in[15];
    const float* ln3b   = (const float*)d_in[16];
    const float* w_f1   = (const float*)d_in[17];
    const float* b_f1   = (const float*)d_in[18];
    const float* w_f2   = (const float*)d_in[19];
    const float* b_f2   = (const float*)d_in[20];
    const float* lnow   = (const float*)d_in[21];
    const float* lnob   = (const float*)d_in[22];

    float *px, *pxn, *pcn, *pqkv, *po, *ph;
    cudaGetSymbolAddress((void**)&px,   g_x);
    cudaGetSymbolAddress((void**)&pxn,  g_xn);
    cudaGetSymbolAddress((void**)&pcn,  g_cn);
    cudaGetSymbolAddress((void**)&pqkv, g_qkv);
    cudaGetSymbolAddress((void**)&po,   g_o);
    cudaGetSymbolAddress((void**)&ph,   g_h);

    cudaFuncSetAttribute(flash_k, cudaFuncAttributeMaxDynamicSharedMemorySize, FSMEM);

    cudaMemcpyAsync(px, in_x, sizeof(float) * CROWS * CD, cudaMemcpyDeviceToDevice);

    dim3 fgrid(CN / 64, CB * CH);

    for (int i = 0; i < CDEPTH; i++) {
        // ---------------- self-attention ----------------
        layernorm_k<<<CROWS, 256>>>(px, pxn, ln1w + i * CD, ln1b + i * CD);
        gemm<0>(pxn, w_qkv + (long)i * CD * 3 * CD, pqkv,
                CROWS, 3 * CD, CD, CD, 3 * CD, 3 * CD);
        flash_k<<<fgrid, 256, FSMEM>>>(pqkv, rpb, po);
        gemm<2>(po, w_so + (long)i * CD * CD, px,
                CROWS, CD, CD, CD, CD, CD,
                b_so + i * CD, px, CD);

        // ---------------- cross-attention ----------------
        layernorm_k<<<CROWS, 256>>>(px,     pxn, ln2w + i * CD, ln2b + i * CD);
        layernorm_k<<<CROWS, 256>>>(in_ctx, pcn, ln2w + i * CD, ln2b + i * CD);
        gemm<0>(pxn, w_q + (long)i * CD * CD, pqkv,
                CROWS, CD, CD, CD, CD, 3 * CD);
        gemm<0>(pcn, w_k + (long)i * CD * CD, pqkv + CD,
                CROWS, CD, CD, CD, CD, 3 * CD);
        gemm<0>(pcn, w_v + (long)i * CD * CD, pqkv + 2 * CD,
                CROWS, CD, CD, CD, CD, 3 * CD);
        flash_k<<<fgrid, 256, FSMEM>>>(pqkv, rpb, po);
        gemm<2>(po, w_co + (long)i * CD * CD, px,
                CROWS, CD, CD, CD, CD, CD,
                b_co + i * CD, px, CD);

        // ---------------- FFN ----------------
        layernorm_k<<<CROWS, 256>>>(px, pxn, ln3w + i * CD, ln3b + i * CD);
        gemm<3>(pxn, w_f1 + (long)i * CD * CFF, ph,
                CROWS, CFF, CD, CD, CFF, CFF,
                b_f1 + i * CFF);
        gemm<2>(ph, w_f2 + (long)i * CFF * CD, px,
                CROWS, CD, CFF, CFF, CD, CD,
                b_f2 + i * CD, px, CD);
    }

    layernorm_k<<<CROWS, 256>>>(px, (float*)d_out, lnow, lnob);
}

// round 4
// speedup vs baseline: 3.8481x; 1.6081x over previous
#include <cuda_runtime.h>
#include <cuda_bf16.h>
#include <math.h>

// ---------------------------------------------------------------------------
// Problem constants
// ---------------------------------------------------------------------------
constexpr int CB     = 2;
constexpr int CN     = 2048;
constexpr int CD     = 768;
constexpr int CH     = 12;
constexpr int CDH    = 64;       // D / H
constexpr int CDEPTH = 4;
constexpr int CFF    = 3072;     // 4*D
constexpr int CROWS  = CB * CN;  // 4096
constexpr float CSCALE = 0.125f; // DH^-0.5
constexpr float CEPS   = 1e-5f;

// ---------------------------------------------------------------------------
// Scratch (static device globals -- no allocations allowed)
// ---------------------------------------------------------------------------
__device__ float g_x  [CROWS * CD];
__device__ float g_xn [CROWS * CD];
__device__ float g_cn [CROWS * CD];
__device__ float g_qkv[CROWS * 3 * CD];
__device__ float g_o  [CROWS * CD];
__device__ float g_h  [CROWS * CFF];

// ---------------------------------------------------------------------------
// Reductions
// ---------------------------------------------------------------------------
__device__ __forceinline__ float warpSum(float v) {
#pragma unroll
    for (int o = 16; o; o >>= 1) v += __shfl_xor_sync(0xffffffffu, v, o);
    return v;
}
__device__ __forceinline__ float blockSum(float v) {
    __shared__ float sh[32];
    int lane = threadIdx.x & 31, w = threadIdx.x >> 5;
    v = warpSum(v);
    if (!lane) sh[w] = v;
    __syncthreads();
    if (w == 0) {
        v = (lane < (int)(blockDim.x >> 5)) ? sh[lane] : 0.f;
        v = warpSum(v);
        if (!lane) sh[0] = v;
    }
    __syncthreads();
    float r = sh[0];
    __syncthreads();
    return r;
}

// ---------------------------------------------------------------------------
// LayerNorm over D=768, one 256-thread block per row
// ---------------------------------------------------------------------------
__global__ void layernorm_k(const float* __restrict__ X, float* __restrict__ Y,
                            const float* __restrict__ w, const float* __restrict__ b) {
    long row = blockIdx.x;
    const float* x = X + row * CD;
    float* y = Y + row * CD;
    int t = threadIdx.x;
    float v0 = x[t], v1 = x[t + 256], v2 = x[t + 512];
    float m = blockSum(v0 + v1 + v2) * (1.0f / CD);
    float d0 = v0 - m, d1 = v1 - m, d2 = v2 - m;
    float var = blockSum(d0 * d0 + d1 * d1 + d2 * d2) * (1.0f / CD);
    float r = rsqrtf(var + CEPS);
    y[t]       = d0 * r * w[t]       + b[t];
    y[t + 256] = d1 * r * w[t + 256] + b[t + 256];
    y[t + 512] = d2 * r * w[t + 512] + b[t + 512];
}

// ---------------------------------------------------------------------------
// tf32 helpers
// ---------------------------------------------------------------------------
__device__ __forceinline__ unsigned f2tf32(float v) {
    unsigned r;
    asm("cvt.rna.tf32.f32 %0, %1;" : "=r"(r) : "f"(v));
    return r;
}
__device__ __forceinline__ void mma_tf32(float* c, const unsigned* a, const unsigned* b) {
    asm volatile(
        "mma.sync.aligned.m16n8k8.row.col.f32.tf32.tf32.f32 "
        "{%0,%1,%2,%3}, {%4,%5,%6,%7}, {%8,%9}, {%0,%1,%2,%3};"
        : "+f"(c[0]), "+f"(c[1]), "+f"(c[2]), "+f"(c[3])
        : "r"(a[0]), "r"(a[1]), "r"(a[2]), "r"(a[3]), "r"(b[0]), "r"(b[1]));
}

// ---------------------------------------------------------------------------
// MMA flash attention (tf32 tensor cores, fp32 softmax).
//   Block: 256 threads (8 warps), 128 query rows, keys streamed in 64-tiles.
//   Each warp owns 16 query rows. Online softmax in accumulator layout.
//   qkv layout: [b*N + n][3*D]; q at col h*DH, k at D + h*DH, v at 2D + h*DH.
// ---------------------------------------------------------------------------
constexpr int FQT  = 128;  // query rows per block
constexpr int FQLD = 68;   // Qs/Ps row stride (words)
constexpr int FKLD = 73;   // Ks row stride
constexpr int FVLD = 72;   // Vs row stride
constexpr int FSM_Q = FQT * FQLD;       // 8704
constexpr int FSM_K = 64 * FKLD;        // 4672
constexpr int FSM_V = 64 * FVLD;        // 4608
constexpr int FSM_P = FQT * FQLD;       // 8704
constexpr int FSMEM = (FSM_Q + FSM_K + FSM_V + FSM_P) * 4; // 106752 bytes

__global__ __launch_bounds__(256, 2) void flashmma_k(const float* __restrict__ qkv,
                                                     const float* __restrict__ rpb,
                                                     float* __restrict__ O) {
    extern __shared__ unsigned smu[];
    unsigned* Qs = smu;
    unsigned* Ks = Qs + FSM_Q;
    unsigned* Vs = Ks + FSM_K;
    unsigned* Ps = Vs + FSM_V;

    int z = blockIdx.y, b = z / CH, h = z % CH;
    const float* qb = qkv + (long)b * CN * 3 * CD + h * CDH;
    const float* kb = qb + CD;
    const float* vb = qb + 2 * CD;
    const float* bias = rpb + (long)h * CN * CN;
    float* ob = O + (long)b * CN * CD + h * CDH;

    int row0 = blockIdx.x * FQT;
    int tid = threadIdx.x;
    int lane = tid & 31, wid = tid >> 5;
    int wrow = wid * 16;
    int g = lane >> 2, t = lane & 3;

    // Stage Q (pre-scaled, tf32) as [row][d]
#pragma unroll
    for (int p = 0; p < 8; p++) {
        int r = p * 16 + (tid >> 4);
        int d = (tid & 15) * 4;
        float4 q4 = *(const float4*)(qb + (long)(row0 + r) * 3 * CD + d);
        uint4 u;
        u.x = f2tf32(q4.x * CSCALE); u.y = f2tf32(q4.y * CSCALE);
        u.z = f2tf32(q4.z * CSCALE); u.w = f2tf32(q4.w * CSCALE);
        *(uint4*)(Qs + r * FQLD + d) = u;
    }

    float Oa[8][4];
#pragma unroll
    for (int nt = 0; nt < 8; nt++)
#pragma unroll
        for (int e = 0; e < 4; e++) Oa[nt][e] = 0.f;
    float m0 = -1e30f, m1 = -1e30f, l0 = 0.f, l1 = 0.f;

    for (int j0 = 0; j0 < CN; j0 += 64) {
        __syncthreads();  // prior PV done; Q staged (iter 0)
        // Stage K transposed [d][key] and V [key][d]
#pragma unroll
        for (int p = 0; p < 4; p++) {
            int ky = p * 16 + (tid >> 4);
            int d = (tid & 15) * 4;
            float4 k4 = *(const float4*)(kb + (long)(j0 + ky) * 3 * CD + d);
            Ks[(d + 0) * FKLD + ky] = f2tf32(k4.x);
            Ks[(d + 1) * FKLD + ky] = f2tf32(k4.y);
            Ks[(d + 2) * FKLD + ky] = f2tf32(k4.z);
            Ks[(d + 3) * FKLD + ky] = f2tf32(k4.w);
            float4 v4 = *(const float4*)(vb + (long)(j0 + ky) * 3 * CD + d);
            uint4 u;
            u.x = f2tf32(v4.x); u.y = f2tf32(v4.y);
            u.z = f2tf32(v4.z); u.w = f2tf32(v4.w);
            *(uint4*)(Vs + ky * FVLD + d) = u;
        }
        __syncthreads();

        // S = Q @ K^T  (warp rows wrow..wrow+15, 8 n-tiles of 8 keys)
        float S[8][4];
#pragma unroll
        for (int nt = 0; nt < 8; nt++)
#pragma unroll
            for (int e = 0; e < 4; e++) S[nt][e] = 0.f;
#pragma unroll
        for (int ks = 0; ks < 8; ks++) {
            int kb8 = ks * 8;
            unsigned af[4];
            int r = wrow + g;
            af[0] = Qs[r * FQLD + kb8 + t];
            af[1] = Qs[(r + 8) * FQLD + kb8 + t];
            af[2] = Qs[r * FQLD + kb8 + t + 4];
            af[3] = Qs[(r + 8) * FQLD + kb8 + t + 4];
#pragma unroll
            for (int nt = 0; nt < 8; nt++) {
                unsigned bf[2];
                bf[0] = Ks[(kb8 + t) * FKLD + nt * 8 + g];
                bf[1] = Ks[(kb8 + t + 4) * FKLD + nt * 8 + g];
                mma_tf32(S[nt], af, bf);
            }
        }

        // + relative position bias (fp32)
        {
            long rA = row0 + wrow + g;
#pragma unroll
            for (int nt = 0; nt < 8; nt++) {
                int col = j0 + nt * 8 + t * 2;
                float2 b0 = __ldg((const float2*)(bias + rA * CN + col));
                float2 b1 = __ldg((const float2*)(bias + (rA + 8) * CN + col));
                S[nt][0] += b0.x; S[nt][1] += b0.y;
                S[nt][2] += b1.x; S[nt][3] += b1.y;
            }
        }

        // Online softmax (rows rA and rA+8 per thread; 4-lane reductions)
        float rm0 = -1e30f, rm1 = -1e30f;
#pragma unroll
        for (int nt = 0; nt < 8; nt++) {
            rm0 = fmaxf(rm0, fmaxf(S[nt][0], S[nt][1]));
            rm1 = fmaxf(rm1, fmaxf(S[nt][2], S[nt][3]));
        }
        rm0 = fmaxf(rm0, __shfl_xor_sync(0xffffffffu, rm0, 1));
        rm0 = fmaxf(rm0, __shfl_xor_sync(0xffffffffu, rm0, 2));
        rm1 = fmaxf(rm1, __shfl_xor_sync(0xffffffffu, rm1, 1));
        rm1 = fmaxf(rm1, __shfl_xor_sync(0xffffffffu, rm1, 2));
        float nm0 = fmaxf(m0, rm0), nm1 = fmaxf(m1, rm1);
        float sc0 = __expf(m0 - nm0), sc1 = __expf(m1 - nm1);
        float rs0 = 0.f, rs1 = 0.f;
#pragma unroll
        for (int nt = 0; nt < 8; nt++) {
            S[nt][0] = __expf(S[nt][0] - nm0);
            S[nt][1] = __expf(S[nt][1] - nm0);
            S[nt][2] = __expf(S[nt][2] - nm1);
            S[nt][3] = __expf(S[nt][3] - nm1);
            rs0 += S[nt][0] + S[nt][1];
            rs1 += S[nt][2] + S[nt][3];
        }
        rs0 += __shfl_xor_sync(0xffffffffu, rs0, 1);
        rs0 += __shfl_xor_sync(0xffffffffu, rs0, 2);
        rs1 += __shfl_xor_sync(0xffffffffu, rs1, 1);
        rs1 += __shfl_xor_sync(0xffffffffu, rs1, 2);
        m0 = nm0; m1 = nm1;
        l0 = l0 * sc0 + rs0;
        l1 = l1 * sc1 + rs1;
#pragma unroll
        for (int nt = 0; nt < 8; nt++) {
            Oa[nt][0] *= sc0; Oa[nt][1] *= sc0;
            Oa[nt][2] *= sc1; Oa[nt][3] *= sc1;
        }

        // Store P (warp-private region) as tf32 [row][key]
        {
            int r = wrow + g;
#pragma unroll
            for (int nt = 0; nt < 8; nt++) {
                int col = nt * 8 + t * 2;
                uint2 p0 = make_uint2(f2tf32(S[nt][0]), f2tf32(S[nt][1]));
                uint2 p1 = make_uint2(f2tf32(S[nt][2]), f2tf32(S[nt][3]));
                *(uint2*)(Ps + r * FQLD + col)       = p0;
                *(uint2*)(Ps + (r + 8) * FQLD + col) = p1;
            }
        }
        __syncwarp();

        // O += P @ V
#pragma unroll
        for (int ks = 0; ks < 8; ks++) {
            int kb8 = ks * 8;
            unsigned af[4];
            int r = wrow + g;
            af[0] = Ps[r * FQLD + kb8 + t];
            af[1] = Ps[(r + 8) * FQLD + kb8 + t];
            af[2] = Ps[r * FQLD + kb8 + t + 4];
            af[3] = Ps[(r + 8) * FQLD + kb8 + t + 4];
#pragma unroll
            for (int nt = 0; nt < 8; nt++) {
                unsigned bf[2];
                bf[0] = Vs[(kb8 + t) * FVLD + nt * 8 + g];
                bf[1] = Vs[(kb8 + t + 4) * FVLD + nt * 8 + g];
                mma_tf32(Oa[nt], af, bf);
            }
        }
    }

    // Normalize and write merged output
    float inv0 = 1.0f / l0, inv1 = 1.0f / l1;
    long rA = row0 + wrow + g;
#pragma unroll
    for (int nt = 0; nt < 8; nt++) {
        int col = nt * 8 + t * 2;
        *(float2*)(ob + rA * CD + col) =
            make_float2(Oa[nt][0] * inv0, Oa[nt][1] * inv0);
        *(float2*)(ob + (rA + 8) * CD + col) =
            make_float2(Oa[nt][2] * inv1, Oa[nt][3] * inv1);
    }
}

// ---------------------------------------------------------------------------
// TF32 tensor-core GEMM (unchanged from passing R3 version).
// ---------------------------------------------------------------------------
constexpr int GBM = 64, GBN = 128, GBK = 32;
constexpr int ALD = GBK + 4;
constexpr int BLD = GBN + 4;

template <int EPI>
__global__ __launch_bounds__(256) void gemm_tf32_k(
        const float* __restrict__ A, const float* __restrict__ B, float* C,
        int M, int N, int K, int lda, int ldb, int ldc,
        const float* __restrict__ P, const float* __restrict__ R, int ldr) {
    __shared__ unsigned As[GBM * ALD];
    __shared__ unsigned Bs[GBK * BLD];

    int tid = threadIdx.x;
    int lane = tid & 31, wid = tid >> 5;
    int wm = wid >> 2, wn = wid & 3;
    int row0 = blockIdx.y * GBM;
    int col0 = blockIdx.x * GBN;

    int ar = tid >> 3, ac = (tid & 7) << 2;
    int br = tid >> 5, bc = (tid & 31) << 2;

    const float* gA = A + (long)(row0 + ar) * lda + ac;
    const float* gB = B + (long)br * ldb + col0 + bc;

    float c[2][4][4];
#pragma unroll
    for (int mt = 0; mt < 2; mt++)
#pragma unroll
        for (int nt = 0; nt < 4; nt++)
#pragma unroll
            for (int e = 0; e < 4; e++) c[mt][nt][e] = 0.f;

    float4 aReg[2], bReg[4];
    aReg[0] = *(const float4*)(gA);
    aReg[1] = *(const float4*)(gA + (long)32 * lda);
#pragma unroll
    for (int i = 0; i < 4; i++)
        bReg[i] = *(const float4*)(gB + (long)(8 * i) * ldb);

    for (int k0 = 0; k0 < K; k0 += GBK) {
        __syncthreads();
#pragma unroll
        for (int h = 0; h < 2; h++) {
            unsigned* d = &As[(ar + 32 * h) * ALD + ac];
            d[0] = f2tf32(h ? aReg[1].x : aReg[0].x);
            d[1] = f2tf32(h ? aReg[1].y : aReg[0].y);
            d[2] = f2tf32(h ? aReg[1].z : aReg[0].z);
            d[3] = f2tf32(h ? aReg[1].w : aReg[0].w);
        }
#pragma unroll
        for (int i = 0; i < 4; i++) {
            unsigned* d = &Bs[(br + 8 * i) * BLD + bc];
            d[0] = f2tf32(bReg[i].x);
            d[1] = f2tf32(bReg[i].y);
            d[2] = f2tf32(bReg[i].z);
            d[3] = f2tf32(bReg[i].w);
        }
        __syncthreads();

        if (k0 + GBK < K) {
            const float* nA = gA + k0 + GBK;
            const float* nB = gB + (long)(k0 + GBK) * ldb;
            aReg[0] = *(const float4*)(nA);
            aReg[1] = *(const float4*)(nA + (long)32 * lda);
#pragma unroll
            for (int i = 0; i < 4; i++)
                bReg[i] = *(const float4*)(nB + (long)(8 * i) * ldb);
        }

#pragma unroll
        for (int ks = 0; ks < 4; ks++) {
            int kb = ks * 8;
            unsigned af[2][4], bf[4][2];
#pragma unroll
            for (int mt = 0; mt < 2; mt++) {
                int r = wm * 32 + mt * 16 + (lane >> 2);
                int cx = kb + (lane & 3);
                af[mt][0] = As[r * ALD + cx];
                af[mt][1] = As[(r + 8) * ALD + cx];
                af[mt][2] = As[r * ALD + cx + 4];
                af[mt][3] = As[(r + 8) * ALD + cx + 4];
            }
#pragma unroll
            for (int nt = 0; nt < 4; nt++) {
                int cn = wn * 32 + nt * 8 + (lane >> 2);
                int rk = kb + (lane & 3);
                bf[nt][0] = Bs[rk * BLD + cn];
                bf[nt][1] = Bs[(rk + 4) * BLD + cn];
            }
#pragma unroll
            for (int mt = 0; mt < 2; mt++)
#pragma unroll
                for (int nt = 0; nt < 4; nt++)
                    mma_tf32(c[mt][nt], af[mt], bf[nt]);
        }
    }

#pragma unroll
    for (int mt = 0; mt < 2; mt++) {
#pragma unroll
        for (int nt = 0; nt < 4; nt++) {
#pragma unroll
            for (int half = 0; half < 2; half++) {
                int gm = row0 + wm * 32 + mt * 16 + (lane >> 2) + 8 * half;
                int gn = col0 + wn * 32 + nt * 8 + (lane & 3) * 2;
                float v0 = c[mt][nt][half * 2 + 0];
                float v1 = c[mt][nt][half * 2 + 1];
                if (EPI == 2) {
                    v0 += P[gn]     + R[(long)gm * ldr + gn];
                    v1 += P[gn + 1] + R[(long)gm * ldr + gn + 1];
                } else if (EPI == 3) {
                    v0 += P[gn];
                    v1 += P[gn + 1];
                    v0 = 0.5f * v0 * (1.0f + erff(v0 * 0.70710678118654752f));
                    v1 = 0.5f * v1 * (1.0f + erff(v1 * 0.70710678118654752f));
                }
                C[(long)gm * ldc + gn]     = v0;
                C[(long)gm * ldc + gn + 1] = v1;
            }
        }
    }
}

template <int EPI>
static void gemm(const float* A, const float* B, float* C,
                 int M, int N, int K, int lda, int ldb, int ldc,
                 const float* P = nullptr, const float* R = nullptr, int ldr = 0) {
    dim3 grid(N / GBN, M / GBM);
    gemm_tf32_k<EPI><<<grid, 256>>>(A, B, C, M, N, K, lda, ldb, ldc, P, R, ldr);
}

// ---------------------------------------------------------------------------
// kernel_launch
// ---------------------------------------------------------------------------
extern "C" void kernel_launch(void* const* d_in, const int* in_sizes, int n_in,
                              void* d_out, int out_size) {
    const float* in_x   = (const float*)d_in[0];
    const float* in_ctx = (const float*)d_in[1];
    const float* rpb    = (const float*)d_in[2];
    const float* ln1w   = (const float*)d_in[3];
    const float* ln1b   = (const float*)d_in[4];
    const float* w_qkv  = (const float*)d_in[5];
    const float* w_so   = (const float*)d_in[6];
    const float* b_so   = (const float*)d_in[7];
    const float* ln2w   = (const float*)d_in[8];
    const float* ln2b   = (const float*)d_in[9];
    const float* w_q    = (const float*)d_in[10];
    const float* w_k    = (const float*)d_in[11];
    const float* w_v    = (const float*)d_in[12];
    const float* w_co   = (const float*)d_in[13];
    const float* b_co   = (const float*)d_in[14];
    const float* ln3w   = (const float*)d_in[15];
    const float* ln3b   = (const float*)d_in[16];
    const float* w_f1   = (const float*)d_in[17];
    const float* b_f1   = (const float*)d_in[18];
    const float* w_f2   = (const float*)d_in[19];
    const float* b_f2   = (const float*)d_in[20];
    const float* lnow   = (const float*)d_in[21];
    const float* lnob   = (const float*)d_in[22];

    float *px, *pxn, *pcn, *pqkv, *po, *ph;
    cudaGetSymbolAddress((void**)&px,   g_x);
    cudaGetSymbolAddress((void**)&pxn,  g_xn);
    cudaGetSymbolAddress((void**)&pcn,  g_cn);
    cudaGetSymbolAddress((void**)&pqkv, g_qkv);
    cudaGetSymbolAddress((void**)&po,   g_o);
    cudaGetSymbolAddress((void**)&ph,   g_h);

    cudaFuncSetAttribute(flashmma_k, cudaFuncAttributeMaxDynamicSharedMemorySize, FSMEM);

    cudaMemcpyAsync(px, in_x, sizeof(float) * CROWS * CD, cudaMemcpyDeviceToDevice);

    dim3 fgrid(CN / FQT, CB * CH);

    for (int i = 0; i < CDEPTH; i++) {
        // ---------------- self-attention ----------------
        layernorm_k<<<CROWS, 256>>>(px, pxn, ln1w + i * CD, ln1b + i * CD);
        gemm<0>(pxn, w_qkv + (long)i * CD * 3 * CD, pqkv,
                CROWS, 3 * CD, CD, CD, 3 * CD, 3 * CD);
        flashmma_k<<<fgrid, 256, FSMEM>>>(pqkv, rpb, po);
        gemm<2>(po, w_so + (long)i * CD * CD, px,
                CROWS, CD, CD, CD, CD, CD,
                b_so + i * CD, px, CD);

        // ---------------- cross-attention ----------------
        layernorm_k<<<CROWS, 256>>>(px,     pxn, ln2w + i * CD, ln2b + i * CD);
        layernorm_k<<<CROWS, 256>>>(in_ctx, pcn, ln2w + i * CD, ln2b + i * CD);
        gemm<0>(pxn, w_q + (long)i * CD * CD, pqkv,
                CROWS, CD, CD, CD, CD, 3 * CD);
        gemm<0>(pcn, w_k + (long)i * CD * CD, pqkv + CD,
                CROWS, CD, CD, CD, CD, 3 * CD);
        gemm<0>(pcn, w_v + (long)i * CD * CD, pqkv + 2 * CD,
                CROWS, CD, CD, CD, CD, 3 * CD);
        flashmma_k<<<fgrid, 256, FSMEM>>>(pqkv, rpb, po);
        gemm<2>(po, w_co + (long)i * CD * CD, px,
                CROWS, CD, CD, CD, CD, CD,
                b_co + i * CD, px, CD);

        // ---------------- FFN ----------------
        layernorm_k<<<CROWS, 256>>>(px, pxn, ln3w + i * CD, ln3b + i * CD);
        gemm<3>(pxn, w_f1 + (long)i * CD * CFF, ph,
                CROWS, CFF, CD, CD, CFF, CFF,
                b_f1 + i * CFF);
        gemm<2>(ph, w_f2 + (long)i * CFF * CD, px,
                CROWS, CD, CFF, CFF, CD, CD,
                b_f2 + i * CD, px, CD);
    }

    layernorm_k<<<CROWS, 256>>>(px, (float*)d_out, lnow, lnob);
}